// round 3
// baseline (speedup 1.0000x reference)
#include <cuda_runtime.h>

// Tree DP on deterministic 4-ary heap: L=4096, B=64, C=2.
// msg[b,cs,k] = lse_{cj}( E[b,cj,j] + msg[b,cj,j] + T[k,j,cs,cj] ), j=(k-1)>>2.
//
// Grid (64 subtrees x 8 batch-groups), 256 threads. Each block owns subtree
// root r in [21,85) + 8 batches; recomputes root->r path in registers, then
// 3 levels via smem. Lane mapping is node-major so E loads / M stores are
// coalesced (batch stride is 32KB -> batch-major mapping was 32 lines/warp).

#define LN  4096
#define BN  64
#define CLN 8192
#define BB  8            // batches per block
#define NG  (BN / BB)

__device__ __forceinline__ float lse2(float a, float b) {
    float mx = fmaxf(a, b);
    float mn = fminf(a, b);
    return mx + __logf(1.0f + __expf(mn - mx));
}

__global__ void __launch_bounds__(256, 1)
k_all(const float* __restrict__ E, const float* __restrict__ T, float* __restrict__ M)
{
    __shared__ float sR[BB][2];           // local(r) = E[r]+msg[r]
    __shared__ float s3[BB][4][2];        // locals of level-3 children of r
    __shared__ float s4[BB][16][2];       // locals of level-4 nodes

    const int tid = threadIdx.x;
    const int r   = 21 + blockIdx.x;      // [21, 85)
    const int b0  = blockIdx.y * BB;

    const int p2 = (r - 1) >> 2;
    const int p1 = (p2 - 1) >> 2;

    // ---------------- prefetch (all statically indexed) ----------------
    // path: tid < 8, batch bb = tid
    float4 tA, tB, tC;
    float eR0, eR1, e10, e11, e20, e21, er0, er1;
    const bool doPath = (tid < BB);
    if (doPath) {
        int b = b0 + tid;
        tA = __ldg((const float4*)T + (p1 * LN + 0));
        tB = __ldg((const float4*)T + (p2 * LN + p1));
        tC = __ldg((const float4*)T + (r  * LN + p2));
        eR0 = E[b * CLN + 0];    eR1 = E[b * CLN + LN + 0];
        e10 = E[b * CLN + p1];   e11 = E[b * CLN + LN + p1];
        e20 = E[b * CLN + p2];   e21 = E[b * CLN + LN + p2];
        er0 = E[b * CLN + r];    er1 = E[b * CLN + LN + r];
    }
    // level 3: tid < 32, node-major: n = tid&3, bb = tid>>2
    float4 t3; float e30, e31; int k3 = 0, bb3 = 0, n3 = 0;
    const bool doL3 = (tid < 4 * BB);
    if (doL3) {
        n3  = tid & 3;
        bb3 = tid >> 2;
        k3  = 4 * r + 1 + n3;
        t3  = __ldg((const float4*)T + (k3 * LN + r));
        int b = b0 + bb3;
        e30 = E[b * CLN + k3];  e31 = E[b * CLN + LN + k3];
    }
    // level 4: tid < 128, n = tid&15, bb = tid>>4  (coalesced E over n)
    float4 t4; float e40, e41; int k4 = 0, bb4 = 0, n4 = 0;
    const bool doL4 = (tid < 16 * BB);
    if (doL4) {
        n4  = tid & 15;
        bb4 = tid >> 4;
        k4  = 16 * r + 5 + n4;
        t4  = __ldg((const float4*)T + (k4 * LN + ((k4 - 1) >> 2)));
        int b = b0 + bb4;
        e40 = E[b * CLN + k4];  e41 = E[b * CLN + LN + k4];
    }
    // level 5: two items/thread, i = tid + it*256; n = i&63, bb = i>>6
    float4 t5[2]; int k5[2]; bool v5[2];
    #pragma unroll
    for (int it = 0; it < 2; ++it) {
        int i = tid + it * 256;
        int n = i & 63;
        k5[it] = 64 * r + 21 + n;
        v5[it] = (k5[it] < LN);
        if (v5[it])
            t5[it] = __ldg((const float4*)T + (k5[it] * LN + ((k5[it] - 1) >> 2)));
    }

    // node 0 never receives a message -> zero it (output is poisoned)
    if (tid < 2 * BB) {
        int b = b0 + (tid >> 1), c = tid & 1;
        M[b * CLN + c * LN] = 0.0f;
    }

    // ---------------- path: root -> p1 -> p2 -> r (registers) ----------------
    if (doPath) {
        int b = b0 + tid;
        float m0 = lse2(eR0 + tA.x, eR1 + tA.y);
        float m1 = lse2(eR0 + tA.z, eR1 + tA.w);
        M[b * CLN + p1] = m0;  M[b * CLN + LN + p1] = m1;
        float l0 = e10 + m0, l1 = e11 + m1;
        m0 = lse2(l0 + tB.x, l1 + tB.y);
        m1 = lse2(l0 + tB.z, l1 + tB.w);
        M[b * CLN + p2] = m0;  M[b * CLN + LN + p2] = m1;
        l0 = e20 + m0;  l1 = e21 + m1;
        m0 = lse2(l0 + tC.x, l1 + tC.y);
        m1 = lse2(l0 + tC.z, l1 + tC.w);
        M[b * CLN + r] = m0;   M[b * CLN + LN + r] = m1;
        sR[tid][0] = er0 + m0;
        sR[tid][1] = er1 + m1;
    }
    __syncthreads();

    // ---------------- level 3 ----------------
    if (doL3) {
        float l0 = sR[bb3][0], l1 = sR[bb3][1];
        float m0 = lse2(l0 + t3.x, l1 + t3.y);
        float m1 = lse2(l0 + t3.z, l1 + t3.w);
        int b = b0 + bb3;
        M[b * CLN + k3] = m0;  M[b * CLN + LN + k3] = m1;
        s3[bb3][n3][0] = e30 + m0;
        s3[bb3][n3][1] = e31 + m1;
    }
    __syncthreads();

    // ---------------- level 4 ----------------
    if (doL4) {
        int pd = n4 >> 2;                          // parent slot in s3
        float l0 = s3[bb4][pd][0], l1 = s3[bb4][pd][1];
        float m0 = lse2(l0 + t4.x, l1 + t4.y);
        float m1 = lse2(l0 + t4.z, l1 + t4.w);
        int b = b0 + bb4;
        M[b * CLN + k4] = m0;  M[b * CLN + LN + k4] = m1;   // coalesced
        s4[bb4][n4][0] = e40 + m0;
        s4[bb4][n4][1] = e41 + m1;
    }
    __syncthreads();

    // ---------------- level 5 (leaves, straight to global) ----------------
    #pragma unroll
    for (int it = 0; it < 2; ++it) {
        if (v5[it]) {
            int i  = tid + it * 256;
            int n  = i & 63;
            int bb = i >> 6;
            int pn = n >> 2;                       // parent slot in s4
            float l0 = s4[bb][pn][0], l1 = s4[bb][pn][1];
            float m0 = lse2(l0 + t5[it].x, l1 + t5[it].y);
            float m1 = lse2(l0 + t5[it].z, l1 + t5[it].w);
            int b = b0 + bb;
            M[b * CLN + k5[it]]      = m0;         // coalesced 128B
            M[b * CLN + LN + k5[it]] = m1;
        }
    }
}

extern "C" void kernel_launch(void* const* d_in, const int* in_sizes, int n_in,
                              void* d_out, int out_size) {
    const float* E = (const float*)d_in[0];   // emissions   [B, C, L] f32
    const float* T = (const float*)d_in[1];   // transitions [L, L, C, C] f32
    float* M = (float*)d_out;                 // messages    [B, C, L] f32

    dim3 grid(64, NG);
    k_all<<<grid, 256>>>(E, T, M);
}